// round 1
// baseline (speedup 1.0000x reference)
#include <cuda_runtime.h>
#include <math.h>

#define NN 10000
#define NE 160000
#define FD 128
#define NRBF 20
#define PI_F 3.14159265358979f

// ---------------- device scratch (static, no runtime alloc) ----------------
__device__ float g_Sbar[NN*FD];
__device__ float g_V[NN*FD*3];
__device__ float g_Valt[NN*FD*3];
__device__ float g_Vb0[NN*FD*3];
__device__ float g_Vb1[NN*FD*3];
__device__ float g_phi[NN*640];
__device__ float g_tmp[NN*256];
__device__ float g_t2[NN*FD];
__device__ float g_a[NN*384];
__device__ float g_uv[NN*FD*3];
__device__ float g_vv[NN*FD*3];
__device__ float g_vn[NN*FD];
__device__ float g_unit[NE*3];
__device__ float g_env[NE];
__device__ float g_rbf[NE*NRBF];
__device__ int   g_cnt[NN];
__device__ int   g_off[NN+1];
__device__ int   g_cur[NN];
__device__ int   g_perm[NE];

// ---------------- CSR build ----------------
__global__ void count_kernel(const int* __restrict__ nbr) {
    int e = blockIdx.x*blockDim.x + threadIdx.x;
    if (e < NE) atomicAdd(&g_cnt[nbr[2*e]], 1);
}

__global__ void scan_kernel() {
    __shared__ int s[1024];
    int t = threadIdx.x;
    const int CH = (NN + 1023) / 1024; // 10
    int base = t*CH;
    int local[CH];
    int sum = 0;
#pragma unroll
    for (int i = 0; i < CH; i++) {
        int v = (base+i < NN) ? g_cnt[base+i] : 0;
        local[i] = v; sum += v;
    }
    s[t] = sum;
    __syncthreads();
    for (int d = 1; d < 1024; d <<= 1) {
        int v = (t >= d) ? s[t-d] : 0;
        __syncthreads();
        s[t] += v;
        __syncthreads();
    }
    int prefix = (t == 0) ? 0 : s[t-1];
#pragma unroll
    for (int i = 0; i < CH; i++) {
        if (base+i < NN) {
            g_off[base+i] = prefix;
            g_cur[base+i] = prefix;
            prefix += local[i];
        }
    }
    if (t == 1023) g_off[NN] = s[1023];
}

__global__ void fill_kernel(const int* __restrict__ nbr) {
    int e = blockIdx.x*blockDim.x + threadIdx.x;
    if (e < NE) {
        int sN = nbr[2*e];
        int p = atomicAdd(&g_cur[sN], 1);
        g_perm[p] = e;
    }
}

// canonicalize per-node edge order (determinism across runs)
__global__ void sort_kernel() {
    int i = blockIdx.x*blockDim.x + threadIdx.x;
    if (i >= NN) return;
    int a = g_off[i], b = g_off[i+1];
    for (int x = a+1; x < b; x++) {
        int v = g_perm[x];
        int y = x-1;
        while (y >= a && g_perm[y] > v) { g_perm[y+1] = g_perm[y]; y--; }
        g_perm[y+1] = v;
    }
}

// ---------------- edge geometry ----------------
__global__ void edge_geom_kernel(const float* __restrict__ xyz,
                                 const int* __restrict__ nbr) {
    int e = blockIdx.x*blockDim.x + threadIdx.x;
    if (e >= NE) return;
    int s = nbr[2*e], d = nbr[2*e+1];
    float dx = xyz[3*d+0] - xyz[3*s+0];
    float dy = xyz[3*d+1] - xyz[3*s+1];
    float dz = xyz[3*d+2] - xyz[3*s+2];
    float dist = sqrtf(dx*dx + dy*dy + dz*dz);
    float inv = 1.0f / dist;
    g_unit[3*e+0] = dx*inv;
    g_unit[3*e+1] = dy*inv;
    g_unit[3*e+2] = dz*inv;
    g_env[e] = (dist < 5.0f) ? 0.5f*(cosf(PI_F*dist*0.2f) + 1.0f) : 0.0f;
    float base = PI_F*0.2f*dist;
#pragma unroll
    for (int k = 0; k < NRBF; k++)
        g_rbf[e*NRBF+k] = sinf((float)(k+1)*base) * inv;
}

// ---------------- fused dense GEMM: C = act(A @ W + b) ----------------
// A is logical [M,K]; columns [0,K0) come from A0 (lda0), [K0,K) from A1 (lda1).
template<int ACT>
__global__ void __launch_bounds__(128) gemm_kernel(
    const float* __restrict__ A0, int lda0,
    const float* __restrict__ A1, int lda1, int K0,
    const float* __restrict__ W, const float* __restrict__ bias,
    float* __restrict__ C, int M, int N, int K)
{
    const int BM = 64, BN = 64, BK = 16;
    __shared__ float As[BK][BM];
    __shared__ float Bs[BK][BN];
    int bm = blockIdx.y*BM, bn = blockIdx.x*BN;
    int t = threadIdx.x;
    int tr = t >> 3;   // 0..15
    int tc = t & 7;    // 0..7
    float acc[4][8];
#pragma unroll
    for (int i = 0; i < 4; i++)
#pragma unroll
        for (int j = 0; j < 8; j++) acc[i][j] = 0.0f;

    for (int k0 = 0; k0 < K; k0 += BK) {
#pragma unroll
        for (int r = 0; r < 8; r++) {
            int idx = r*128 + t;
            int k = idx >> 6, m = idx & 63;
            int gm = bm + m, gk = k0 + k;
            float v = 0.0f;
            if (gm < M)
                v = (gk < K0) ? A0[(size_t)gm*lda0 + gk]
                              : A1[(size_t)gm*lda1 + (gk - K0)];
            As[k][m] = v;
        }
#pragma unroll
        for (int r = 0; r < 8; r++) {
            int idx = r*128 + t;
            int k = idx >> 6, n = idx & 63;
            Bs[k][n] = W[(size_t)(k0+k)*N + bn + n];
        }
        __syncthreads();
#pragma unroll
        for (int k = 0; k < BK; k++) {
            float a[4], b[8];
#pragma unroll
            for (int i = 0; i < 4; i++) a[i] = As[k][tr*4 + i];
#pragma unroll
            for (int j = 0; j < 8; j++) b[j] = Bs[k][tc*8 + j];
#pragma unroll
            for (int i = 0; i < 4; i++)
#pragma unroll
                for (int j = 0; j < 8; j++)
                    acc[i][j] = fmaf(a[i], b[j], acc[i][j]);
        }
        __syncthreads();
    }
#pragma unroll
    for (int i = 0; i < 4; i++) {
        int gm = bm + tr*4 + i;
        if (gm >= M) continue;
#pragma unroll
        for (int j = 0; j < 8; j++) {
            int gn = bn + tc*8 + j;
            float v = acc[i][j] + bias[gn];
            if (ACT) v = v / (1.0f + expf(-v));  // silu
            C[(size_t)gm*N + gn] = v;
        }
    }
}

// ---------------- edge aggregation (gather over CSR) ----------------
__global__ void __launch_bounds__(128, 3) agg_kernel(
    const float* __restrict__ phi, const float* __restrict__ dW,
    const float* __restrict__ db, const int* __restrict__ nbr,
    const float* __restrict__ Vin, float* __restrict__ Vout,
    const float* __restrict__ Vbin, float* __restrict__ Vbout,
    float* __restrict__ H, float* __restrict__ Sbar)
{
    const int f = threadIdx.x;
    float wreg[5][NRBF];
    float breg[5];
#pragma unroll
    for (int c = 0; c < 5; c++) {
        breg[c] = db[c*128 + f];
#pragma unroll
        for (int k = 0; k < NRBF; k++)
            wreg[c][k] = dW[k*640 + c*128 + f];
    }
    int i0 = blockIdx.x * 8;
    for (int ii = 0; ii < 8; ii++) {
        int i = i0 + ii;
        if (i >= NN) return;
        float aH = 0.f, aS = 0.f;
        float aV0 = 0.f, aV1 = 0.f, aV2 = 0.f;
        float aB0 = 0.f, aB1 = 0.f, aB2 = 0.f;
        int e0 = g_off[i], e1 = g_off[i+1];
        for (int p = e0; p < e1; p++) {
            int e = g_perm[p];
            int j = nbr[2*e+1];
            float ev = g_env[e];
            float u0 = g_unit[3*e+0], u1 = g_unit[3*e+1], u2 = g_unit[3*e+2];
            float r[NRBF];
#pragma unroll
            for (int k = 0; k < NRBF; k++) r[k] = g_rbf[e*NRBF + k];
            float w[5];
#pragma unroll
            for (int c = 0; c < 5; c++) {
                float s = breg[c];
#pragma unroll
                for (int k = 0; k < NRBF; k++)
                    s = fmaf(r[k], wreg[c][k], s);
                w[c] = s * ev;
            }
            const float* pj = phi + (size_t)j*640 + f;
            float i0v = pj[0]   * w[0];
            float i1v = pj[128] * w[1];
            float i2v = pj[256] * w[2];
            float i3v = pj[384] * w[3];
            float i4v = pj[512] * w[4];
            aH += i1v;
            aS += i3v;
            const float* vj = Vin  + ((size_t)j*128 + f)*3;
            const float* bj = Vbin + ((size_t)j*128 + f)*3;
            float ua0 = i2v*u0, ua1 = i2v*u1, ua2 = i2v*u2;
            aV0 += ua0 + i0v*vj[0];
            aV1 += ua1 + i0v*vj[1];
            aV2 += ua2 + i0v*vj[2];
            aB0 += ua0 + i4v*bj[0];
            aB1 += ua1 + i4v*bj[1];
            aB2 += ua2 + i4v*bj[2];
        }
        size_t hi = (size_t)i*128 + f;
        H[hi]    += aH;
        Sbar[hi] += aS;
        size_t vi = hi*3;
        Vout[vi+0]  = Vin[vi+0]  + aV0;
        Vout[vi+1]  = Vin[vi+1]  + aV1;
        Vout[vi+2]  = Vin[vi+2]  + aV2;
        Vbout[vi+0] = Vbin[vi+0] + aB0;
        Vbout[vi+1] = Vbin[vi+1] + aB1;
        Vbout[vi+2] = Vbin[vi+2] + aB2;
    }
}

// ---------------- u_v / v_v / v_norm ----------------
__global__ void __launch_bounds__(128) upd_uv_kernel(
    const float* __restrict__ Vc, const float* __restrict__ U,
    const float* __restrict__ Wt,
    float* __restrict__ uv, float* __restrict__ vv, float* __restrict__ vn)
{
    __shared__ float sV[4][384];
    int g = threadIdx.x;
    int n0 = blockIdx.x * 4;   // NN % 4 == 0
#pragma unroll
    for (int n = 0; n < 4; n++) {
        int node = n0 + n;
#pragma unroll
        for (int r = 0; r < 3; r++)
            sV[n][r*128 + g] = Vc[(size_t)node*384 + r*128 + g];
    }
    __syncthreads();
    float aU[4][3] = {}, aV[4][3] = {};
    for (int f = 0; f < 128; f++) {
        float u = U[f*128 + g];
        float w = Wt[f*128 + g];
#pragma unroll
        for (int n = 0; n < 4; n++) {
            float v0 = sV[n][f*3+0], v1 = sV[n][f*3+1], v2 = sV[n][f*3+2];
            aU[n][0] = fmaf(u, v0, aU[n][0]);
            aU[n][1] = fmaf(u, v1, aU[n][1]);
            aU[n][2] = fmaf(u, v2, aU[n][2]);
            aV[n][0] = fmaf(w, v0, aV[n][0]);
            aV[n][1] = fmaf(w, v1, aV[n][1]);
            aV[n][2] = fmaf(w, v2, aV[n][2]);
        }
    }
#pragma unroll
    for (int n = 0; n < 4; n++) {
        int node = n0 + n;
        float nv = sqrtf(aV[n][0]*aV[n][0] + aV[n][1]*aV[n][1] +
                         aV[n][2]*aV[n][2] + 1e-15f);
        vn[(size_t)node*128 + g] = nv;
        size_t b = ((size_t)node*128 + g)*3;
        uv[b+0] = aU[n][0]; uv[b+1] = aU[n][1]; uv[b+2] = aU[n][2];
        vv[b+0] = aV[n][0]; vv[b+1] = aV[n][1]; vv[b+2] = aV[n][2];
    }
}

// ---------------- final gated update ----------------
__global__ void final_upd_kernel(float* __restrict__ H, float* __restrict__ V,
                                 const float* __restrict__ uv,
                                 const float* __restrict__ vv,
                                 const float* __restrict__ a)
{
    int idx = blockIdx.x*blockDim.x + threadIdx.x;
    if (idx >= NN*128) return;
    int n = idx >> 7, g = idx & 127;
    float a0 = a[(size_t)n*384 + g];
    float a1 = a[(size_t)n*384 + 128 + g];
    float a2 = a[(size_t)n*384 + 256 + g];
    size_t b = (size_t)idx*3;
    float u0 = uv[b], u1 = uv[b+1], u2 = uv[b+2];
    float dot = u0*vv[b] + u1*vv[b+1] + u2*vv[b+2];
    H[idx] += fmaf(a1, dot, a2);
    V[b+0] += a0*u0;
    V[b+1] += a0*u1;
    V[b+2] += a0*u2;
}

// ---------------- host ----------------
extern "C" void kernel_launch(void* const* d_in, const int* in_sizes, int n_in,
                              void* d_out, int out_size) {
    const float* xyz    = (const float*)d_in[0];
    const int*   nbr    = (const int*)  d_in[1];
    const float* Hin    = (const float*)d_in[3];
    const float* msg_W1 = (const float*)d_in[4];
    const float* msg_b1 = (const float*)d_in[5];
    const float* msg_W2 = (const float*)d_in[6];
    const float* msg_b2 = (const float*)d_in[7];
    const float* dist_W = (const float*)d_in[8];
    const float* dist_b = (const float*)d_in[9];
    const float* upd_U  = (const float*)d_in[10];
    const float* upd_Vw = (const float*)d_in[11];
    const float* upd_W1 = (const float*)d_in[12];
    const float* upd_b1 = (const float*)d_in[13];
    const float* upd_W2 = (const float*)d_in[14];
    const float* upd_b2 = (const float*)d_in[15];

    float* outH = (float*)d_out;

    float *Sbar, *V, *Valt, *Vb0, *Vb1, *phi, *tmp, *t2, *aBuf, *uv, *vv, *vn;
    int* cnt;
    cudaGetSymbolAddress((void**)&Sbar, g_Sbar);
    cudaGetSymbolAddress((void**)&V,    g_V);
    cudaGetSymbolAddress((void**)&Valt, g_Valt);
    cudaGetSymbolAddress((void**)&Vb0,  g_Vb0);
    cudaGetSymbolAddress((void**)&Vb1,  g_Vb1);
    cudaGetSymbolAddress((void**)&phi,  g_phi);
    cudaGetSymbolAddress((void**)&tmp,  g_tmp);
    cudaGetSymbolAddress((void**)&t2,   g_t2);
    cudaGetSymbolAddress((void**)&aBuf, g_a);
    cudaGetSymbolAddress((void**)&uv,   g_uv);
    cudaGetSymbolAddress((void**)&vv,   g_vv);
    cudaGetSymbolAddress((void**)&vn,   g_vn);
    cudaGetSymbolAddress((void**)&cnt,  g_cnt);

    // where does V output go?
    float* outV = (out_size >= NN*FD + NN*FD*3) ? (outH + NN*FD) : Valt;

    // init (must re-run every call: scratch was mutated last call)
    cudaMemsetAsync(cnt,  0, NN*sizeof(int));
    cudaMemsetAsync(Sbar, 0, (size_t)NN*FD*sizeof(float));
    cudaMemsetAsync(V,    0, (size_t)NN*FD*3*sizeof(float));
    cudaMemsetAsync(Vb0,  0, (size_t)NN*FD*3*sizeof(float));
    cudaMemcpyAsync(outH, Hin, (size_t)NN*FD*sizeof(float),
                    cudaMemcpyDeviceToDevice);

    count_kernel<<<(NE+255)/256, 256>>>(nbr);
    scan_kernel<<<1, 1024>>>();
    fill_kernel<<<(NE+255)/256, 256>>>(nbr);
    sort_kernel<<<(NN+127)/128, 128>>>();
    edge_geom_kernel<<<(NE+127)/128, 128>>>(xyz, nbr);

    float* Vbufs[2] = {V,   outV};
    float* Bbufs[2] = {Vb0, Vb1};

    const int MT = (NN + 63) / 64;  // 157

    for (int l = 0; l < 3; l++) {
        const float* W1  = msg_W1 + (size_t)l*256*256;
        const float* b1  = msg_b1 + (size_t)l*256;
        const float* W2  = msg_W2 + (size_t)l*256*640;
        const float* b2  = msg_b2 + (size_t)l*640;
        const float* dWl = dist_W + (size_t)l*20*640;
        const float* dbl = dist_b + (size_t)l*640;
        const float* Ul  = upd_U  + (size_t)l*128*128;
        const float* Wtl = upd_Vw + (size_t)l*128*128;
        const float* uW1 = upd_W1 + (size_t)l*256*128;
        const float* ub1 = upd_b1 + (size_t)l*128;
        const float* uW2 = upd_W2 + (size_t)l*128*384;
        const float* ub2 = upd_b2 + (size_t)l*384;

        float* Vin   = Vbufs[l & 1];
        float* Vout_ = Vbufs[(l+1) & 1];
        float* Bin   = Bbufs[l & 1];
        float* Bout  = Bbufs[(l+1) & 1];

        // tmp = silu([H|Sbar] @ W1 + b1)
        gemm_kernel<1><<<dim3(256/64, MT), 128>>>(outH, 128, Sbar, 128, 128,
                                                  W1, b1, tmp, NN, 256, 256);
        // phi = tmp @ W2 + b2
        gemm_kernel<0><<<dim3(640/64, MT), 128>>>(tmp, 256, tmp, 256, 256,
                                                  W2, b2, phi, NN, 640, 256);
        // message aggregation
        agg_kernel<<<(NN+7)/8, 128>>>(phi, dWl, dbl, nbr,
                                      Vin, Vout_, Bin, Bout, outH, Sbar);
        // u_v, v_v, v_norm
        upd_uv_kernel<<<NN/4, 128>>>(Vout_, Ul, Wtl, uv, vv, vn);
        // t2 = silu([H|v_norm] @ uW1 + ub1)
        gemm_kernel<1><<<dim3(128/64, MT), 128>>>(outH, 128, vn, 128, 128,
                                                  uW1, ub1, t2, NN, 128, 256);
        // a = t2 @ uW2 + ub2
        gemm_kernel<0><<<dim3(384/64, MT), 128>>>(t2, 128, t2, 128, 128,
                                                  uW2, ub2, aBuf, NN, 384, 128);
        // H += a1*dot + a2 ; V += a0*u_v
        final_upd_kernel<<<(NN*128+255)/256, 256>>>(outH, Vout_, uv, vv, aBuf);
    }
}

// round 2
// speedup vs baseline: 1.4549x; 1.4549x over previous
#include <cuda_runtime.h>
#include <math.h>

#define NN 10000
#define NE 160000
#define FD 128
#define NRBF 20
#define PI_F 3.14159265358979f

// ---------------- device scratch (static, no runtime alloc) ----------------
__device__ float g_Sbar[NN*FD];
__device__ float g_V[NN*FD*3];
__device__ float g_Valt[NN*FD*3];
__device__ float g_Vb0[NN*FD*3];
__device__ float g_Vb1[NN*FD*3];
__device__ float g_phi[NN*640];
__device__ float g_tmp[NN*256];
__device__ float g_t2[NN*FD];
__device__ float g_a[NN*384];
__device__ float g_uv[NN*FD*3];
__device__ float g_vv[NN*FD*3];
__device__ float g_vn[NN*FD];
__device__ float g_unit[NE*3];
__device__ float g_env[NE];
__device__ float g_rbf[NE*NRBF];
__device__ int   g_cnt[NN];
__device__ int   g_off[NN+1];
__device__ int   g_cur[NN];
__device__ int   g_perm[NE];

// ---------------- CSR build ----------------
__global__ void count_kernel(const int* __restrict__ nbr) {
    int e = blockIdx.x*blockDim.x + threadIdx.x;
    if (e < NE) atomicAdd(&g_cnt[nbr[2*e]], 1);
}

__global__ void scan_kernel() {
    __shared__ int s[1024];
    int t = threadIdx.x;
    const int CH = (NN + 1023) / 1024; // 10
    int base = t*CH;
    int local[CH];
    int sum = 0;
#pragma unroll
    for (int i = 0; i < CH; i++) {
        int v = (base+i < NN) ? g_cnt[base+i] : 0;
        local[i] = v; sum += v;
    }
    s[t] = sum;
    __syncthreads();
    for (int d = 1; d < 1024; d <<= 1) {
        int v = (t >= d) ? s[t-d] : 0;
        __syncthreads();
        s[t] += v;
        __syncthreads();
    }
    int prefix = (t == 0) ? 0 : s[t-1];
#pragma unroll
    for (int i = 0; i < CH; i++) {
        if (base+i < NN) {
            g_off[base+i] = prefix;
            g_cur[base+i] = prefix;
            prefix += local[i];
        }
    }
    if (t == 1023) g_off[NN] = s[1023];
}

__global__ void fill_kernel(const int* __restrict__ nbr) {
    int e = blockIdx.x*blockDim.x + threadIdx.x;
    if (e < NE) {
        int sN = nbr[2*e];
        int p = atomicAdd(&g_cur[sN], 1);
        g_perm[p] = e;
    }
}

// canonicalize per-node edge order (determinism across runs)
__global__ void sort_kernel() {
    int i = blockIdx.x*blockDim.x + threadIdx.x;
    if (i >= NN) return;
    int a = g_off[i], b = g_off[i+1];
    for (int x = a+1; x < b; x++) {
        int v = g_perm[x];
        int y = x-1;
        while (y >= a && g_perm[y] > v) { g_perm[y+1] = g_perm[y]; y--; }
        g_perm[y+1] = v;
    }
}

// ---------------- edge geometry ----------------
__global__ void edge_geom_kernel(const float* __restrict__ xyz,
                                 const int* __restrict__ nbr) {
    int e = blockIdx.x*blockDim.x + threadIdx.x;
    if (e >= NE) return;
    int s = nbr[2*e], d = nbr[2*e+1];
    float dx = xyz[3*d+0] - xyz[3*s+0];
    float dy = xyz[3*d+1] - xyz[3*s+1];
    float dz = xyz[3*d+2] - xyz[3*s+2];
    float dist = sqrtf(dx*dx + dy*dy + dz*dz);
    float inv = 1.0f / dist;
    g_unit[3*e+0] = dx*inv;
    g_unit[3*e+1] = dy*inv;
    g_unit[3*e+2] = dz*inv;
    g_env[e] = (dist < 5.0f) ? 0.5f*(cosf(PI_F*dist*0.2f) + 1.0f) : 0.0f;
    float base = PI_F*0.2f*dist;
#pragma unroll
    for (int k = 0; k < NRBF; k++)
        g_rbf[e*NRBF+k] = sinf((float)(k+1)*base) * inv;
}

// ---------------- high-throughput fused GEMM ----------------
// C[M,N] = act(A @ W + b). A logical [M,K]: cols [0,K0) from A0, rest from A1.
// Tile BMxBNxBK = BMx128x16, 8x8 microtile, double-buffered smem.
// Requires: N % 128 == 0, K % 16 == 0, K0 % 8 == 0.
template<int BM, int ACT>
__global__ void __launch_bounds__(BM*2, 256/BM) gemm_tc(
    const float* __restrict__ A0, int lda0,
    const float* __restrict__ A1, int lda1, int K0,
    const float* __restrict__ W, const float* __restrict__ bias,
    float* __restrict__ C, int M, int N, int K)
{
    const int BN = 128, BK = 16;
    const int NT = BM*2;            // threads
    const int BLD = 2048/NT;        // B floats per thread per stage
    __shared__ float As[2][BK][BM];
    __shared__ float Bs[2][BK][BN];

    int t  = threadIdx.x;
    int bm = blockIdx.y*BM, bn = blockIdx.x*BN;
    int tx = t & 15;                // 0..15  -> col block
    int ty = t >> 4;                // 0..BM/8-1 -> row block

    // A-load mapping: one row, 8 consecutive k per thread
    int am  = t % BM;
    int acg = t / BM;               // 0 or 1
    int gmA = bm + am;
    bool mok = gmA < M;

    float acc[8][8];
#pragma unroll
    for (int i = 0; i < 8; i++)
#pragma unroll
        for (int j = 0; j < 8; j++) acc[i][j] = 0.0f;

    float4 ra[2];
    float4 rb[BLD/4];

    // ---- prologue: load k-block 0 ----
    {
        int gk = acg*8;
        if (mok) {
            const float* p = (gk < K0) ? (A0 + (size_t)gmA*lda0 + gk)
                                       : (A1 + (size_t)gmA*lda1 + (gk - K0));
            ra[0] = *(const float4*)p;
            ra[1] = *(const float4*)(p+4);
        } else {
            ra[0] = make_float4(0,0,0,0); ra[1] = ra[0];
        }
#pragma unroll
        for (int i = 0; i < BLD/4; i++) {
            int idx = t*BLD + i*4;
            int k = idx >> 7, n = idx & 127;
            rb[i] = *(const float4*)(W + (size_t)k*N + bn + n);
        }
    }
    // store stage 0
    {
        float* ap = &As[0][acg*8][am];
        ap[0*BM] = ra[0].x; ap[1*BM] = ra[0].y; ap[2*BM] = ra[0].z; ap[3*BM] = ra[0].w;
        ap[4*BM] = ra[1].x; ap[5*BM] = ra[1].y; ap[6*BM] = ra[1].z; ap[7*BM] = ra[1].w;
#pragma unroll
        for (int i = 0; i < BLD/4; i++) {
            int idx = t*BLD + i*4;
            int k = idx >> 7, n = idx & 127;
            *(float4*)&Bs[0][k][n] = rb[i];
        }
    }
    __syncthreads();

    int st = 0;
    for (int k0 = BK; k0 < K; k0 += BK) {
        // prefetch next k-block into registers
        {
            int gk = k0 + acg*8;
            if (mok) {
                const float* p = (gk < K0) ? (A0 + (size_t)gmA*lda0 + gk)
                                           : (A1 + (size_t)gmA*lda1 + (gk - K0));
                ra[0] = *(const float4*)p;
                ra[1] = *(const float4*)(p+4);
            }
#pragma unroll
            for (int i = 0; i < BLD/4; i++) {
                int idx = t*BLD + i*4;
                int k = idx >> 7, n = idx & 127;
                rb[i] = *(const float4*)(W + (size_t)(k0+k)*N + bn + n);
            }
        }
        // compute current stage
#pragma unroll
        for (int kk = 0; kk < BK; kk++) {
            float4 a0 = *(const float4*)&As[st][kk][ty*8];
            float4 a1 = *(const float4*)&As[st][kk][ty*8+4];
            float4 b0 = *(const float4*)&Bs[st][kk][tx*8];
            float4 b1 = *(const float4*)&Bs[st][kk][tx*8+4];
            float av[8] = {a0.x,a0.y,a0.z,a0.w,a1.x,a1.y,a1.z,a1.w};
            float bv[8] = {b0.x,b0.y,b0.z,b0.w,b1.x,b1.y,b1.z,b1.w};
#pragma unroll
            for (int i = 0; i < 8; i++)
#pragma unroll
                for (int j = 0; j < 8; j++)
                    acc[i][j] = fmaf(av[i], bv[j], acc[i][j]);
        }
        // write next stage
        {
            int ns = st ^ 1;
            float* ap = &As[ns][acg*8][am];
            ap[0*BM] = ra[0].x; ap[1*BM] = ra[0].y; ap[2*BM] = ra[0].z; ap[3*BM] = ra[0].w;
            ap[4*BM] = ra[1].x; ap[5*BM] = ra[1].y; ap[6*BM] = ra[1].z; ap[7*BM] = ra[1].w;
#pragma unroll
            for (int i = 0; i < BLD/4; i++) {
                int idx = t*BLD + i*4;
                int k = idx >> 7, n = idx & 127;
                *(float4*)&Bs[ns][k][n] = rb[i];
            }
        }
        __syncthreads();
        st ^= 1;
    }
    // last stage compute
#pragma unroll
    for (int kk = 0; kk < BK; kk++) {
        float4 a0 = *(const float4*)&As[st][kk][ty*8];
        float4 a1 = *(const float4*)&As[st][kk][ty*8+4];
        float4 b0 = *(const float4*)&Bs[st][kk][tx*8];
        float4 b1 = *(const float4*)&Bs[st][kk][tx*8+4];
        float av[8] = {a0.x,a0.y,a0.z,a0.w,a1.x,a1.y,a1.z,a1.w};
        float bv[8] = {b0.x,b0.y,b0.z,b0.w,b1.x,b1.y,b1.z,b1.w};
#pragma unroll
        for (int i = 0; i < 8; i++)
#pragma unroll
            for (int j = 0; j < 8; j++)
                acc[i][j] = fmaf(av[i], bv[j], acc[i][j]);
    }

    // epilogue
    float bj[8];
#pragma unroll
    for (int j = 0; j < 8; j++) bj[j] = bias[bn + tx*8 + j];
#pragma unroll
    for (int i = 0; i < 8; i++) {
        int gm = bm + ty*8 + i;
        if (gm >= M) continue;
        float* cp = C + (size_t)gm*N + bn + tx*8;
#pragma unroll
        for (int j = 0; j < 8; j += 4) {
            float4 v;
            v.x = acc[i][j+0] + bj[j+0];
            v.y = acc[i][j+1] + bj[j+1];
            v.z = acc[i][j+2] + bj[j+2];
            v.w = acc[i][j+3] + bj[j+3];
            if (ACT) {
                v.x = v.x / (1.0f + expf(-v.x));
                v.y = v.y / (1.0f + expf(-v.y));
                v.z = v.z / (1.0f + expf(-v.z));
                v.w = v.w / (1.0f + expf(-v.w));
            }
            *(float4*)(cp + j) = v;
        }
    }
}

// ---------------- edge aggregation (gather over CSR) ----------------
__global__ void __launch_bounds__(128, 3) agg_kernel(
    const float* __restrict__ phi, const float* __restrict__ dW,
    const float* __restrict__ db, const int* __restrict__ nbr,
    const float* __restrict__ Vin, float* __restrict__ Vout,
    const float* __restrict__ Vbin, float* __restrict__ Vbout,
    float* __restrict__ H, float* __restrict__ Sbar)
{
    const int f = threadIdx.x;
    float wreg[5][NRBF];
    float breg[5];
#pragma unroll
    for (int c = 0; c < 5; c++) {
        breg[c] = db[c*128 + f];
#pragma unroll
        for (int k = 0; k < NRBF; k++)
            wreg[c][k] = dW[k*640 + c*128 + f];
    }
    int i0 = blockIdx.x * 8;
    for (int ii = 0; ii < 8; ii++) {
        int i = i0 + ii;
        if (i >= NN) return;
        float aH = 0.f, aS = 0.f;
        float aV0 = 0.f, aV1 = 0.f, aV2 = 0.f;
        float aB0 = 0.f, aB1 = 0.f, aB2 = 0.f;
        int e0 = g_off[i], e1 = g_off[i+1];
        for (int p = e0; p < e1; p++) {
            int e = g_perm[p];
            int j = nbr[2*e+1];
            float ev = g_env[e];
            float u0 = g_unit[3*e+0], u1 = g_unit[3*e+1], u2 = g_unit[3*e+2];
            float r[NRBF];
#pragma unroll
            for (int k = 0; k < NRBF; k++) r[k] = g_rbf[e*NRBF + k];
            float w[5];
#pragma unroll
            for (int c = 0; c < 5; c++) {
                float s = breg[c];
#pragma unroll
                for (int k = 0; k < NRBF; k++)
                    s = fmaf(r[k], wreg[c][k], s);
                w[c] = s * ev;
            }
            const float* pj = phi + (size_t)j*640 + f;
            float i0v = pj[0]   * w[0];
            float i1v = pj[128] * w[1];
            float i2v = pj[256] * w[2];
            float i3v = pj[384] * w[3];
            float i4v = pj[512] * w[4];
            aH += i1v;
            aS += i3v;
            const float* vj = Vin  + ((size_t)j*128 + f)*3;
            const float* bj = Vbin + ((size_t)j*128 + f)*3;
            float ua0 = i2v*u0, ua1 = i2v*u1, ua2 = i2v*u2;
            aV0 += ua0 + i0v*vj[0];
            aV1 += ua1 + i0v*vj[1];
            aV2 += ua2 + i0v*vj[2];
            aB0 += ua0 + i4v*bj[0];
            aB1 += ua1 + i4v*bj[1];
            aB2 += ua2 + i4v*bj[2];
        }
        size_t hi = (size_t)i*128 + f;
        H[hi]    += aH;
        Sbar[hi] += aS;
        size_t vi = hi*3;
        Vout[vi+0]  = Vin[vi+0]  + aV0;
        Vout[vi+1]  = Vin[vi+1]  + aV1;
        Vout[vi+2]  = Vin[vi+2]  + aV2;
        Vbout[vi+0] = Vbin[vi+0] + aB0;
        Vbout[vi+1] = Vbin[vi+1] + aB1;
        Vbout[vi+2] = Vbin[vi+2] + aB2;
    }
}

// ---------------- u_v / v_v / v_norm ----------------
__global__ void __launch_bounds__(128) upd_uv_kernel(
    const float* __restrict__ Vc, const float* __restrict__ U,
    const float* __restrict__ Wt,
    float* __restrict__ uv, float* __restrict__ vv, float* __restrict__ vn)
{
    __shared__ float sV[4][384];
    int g = threadIdx.x;
    int n0 = blockIdx.x * 4;   // NN % 4 == 0
#pragma unroll
    for (int n = 0; n < 4; n++) {
        int node = n0 + n;
#pragma unroll
        for (int r = 0; r < 3; r++)
            sV[n][r*128 + g] = Vc[(size_t)node*384 + r*128 + g];
    }
    __syncthreads();
    float aU[4][3] = {}, aV[4][3] = {};
    for (int f = 0; f < 128; f++) {
        float u = U[f*128 + g];
        float w = Wt[f*128 + g];
#pragma unroll
        for (int n = 0; n < 4; n++) {
            float v0 = sV[n][f*3+0], v1 = sV[n][f*3+1], v2 = sV[n][f*3+2];
            aU[n][0] = fmaf(u, v0, aU[n][0]);
            aU[n][1] = fmaf(u, v1, aU[n][1]);
            aU[n][2] = fmaf(u, v2, aU[n][2]);
            aV[n][0] = fmaf(w, v0, aV[n][0]);
            aV[n][1] = fmaf(w, v1, aV[n][1]);
            aV[n][2] = fmaf(w, v2, aV[n][2]);
        }
    }
#pragma unroll
    for (int n = 0; n < 4; n++) {
        int node = n0 + n;
        float nv = sqrtf(aV[n][0]*aV[n][0] + aV[n][1]*aV[n][1] +
                         aV[n][2]*aV[n][2] + 1e-15f);
        vn[(size_t)node*128 + g] = nv;
        size_t b = ((size_t)node*128 + g)*3;
        uv[b+0] = aU[n][0]; uv[b+1] = aU[n][1]; uv[b+2] = aU[n][2];
        vv[b+0] = aV[n][0]; vv[b+1] = aV[n][1]; vv[b+2] = aV[n][2];
    }
}

// ---------------- final gated update ----------------
__global__ void final_upd_kernel(float* __restrict__ H, float* __restrict__ V,
                                 const float* __restrict__ uv,
                                 const float* __restrict__ vv,
                                 const float* __restrict__ a)
{
    int idx = blockIdx.x*blockDim.x + threadIdx.x;
    if (idx >= NN*128) return;
    int n = idx >> 7, g = idx & 127;
    float a0 = a[(size_t)n*384 + g];
    float a1 = a[(size_t)n*384 + 128 + g];
    float a2 = a[(size_t)n*384 + 256 + g];
    size_t b = (size_t)idx*3;
    float u0 = uv[b], u1 = uv[b+1], u2 = uv[b+2];
    float dot = u0*vv[b] + u1*vv[b+1] + u2*vv[b+2];
    H[idx] += fmaf(a1, dot, a2);
    V[b+0] += a0*u0;
    V[b+1] += a0*u1;
    V[b+2] += a0*u2;
}

// ---------------- host ----------------
extern "C" void kernel_launch(void* const* d_in, const int* in_sizes, int n_in,
                              void* d_out, int out_size) {
    const float* xyz    = (const float*)d_in[0];
    const int*   nbr    = (const int*)  d_in[1];
    const float* Hin    = (const float*)d_in[3];
    const float* msg_W1 = (const float*)d_in[4];
    const float* msg_b1 = (const float*)d_in[5];
    const float* msg_W2 = (const float*)d_in[6];
    const float* msg_b2 = (const float*)d_in[7];
    const float* dist_W = (const float*)d_in[8];
    const float* dist_b = (const float*)d_in[9];
    const float* upd_U  = (const float*)d_in[10];
    const float* upd_Vw = (const float*)d_in[11];
    const float* upd_W1 = (const float*)d_in[12];
    const float* upd_b1 = (const float*)d_in[13];
    const float* upd_W2 = (const float*)d_in[14];
    const float* upd_b2 = (const float*)d_in[15];

    float* outH = (float*)d_out;

    float *Sbar, *V, *Valt, *Vb0, *Vb1, *phi, *tmp, *t2, *aBuf, *uv, *vv, *vn;
    int* cnt;
    cudaGetSymbolAddress((void**)&Sbar, g_Sbar);
    cudaGetSymbolAddress((void**)&V,    g_V);
    cudaGetSymbolAddress((void**)&Valt, g_Valt);
    cudaGetSymbolAddress((void**)&Vb0,  g_Vb0);
    cudaGetSymbolAddress((void**)&Vb1,  g_Vb1);
    cudaGetSymbolAddress((void**)&phi,  g_phi);
    cudaGetSymbolAddress((void**)&tmp,  g_tmp);
    cudaGetSymbolAddress((void**)&t2,   g_t2);
    cudaGetSymbolAddress((void**)&aBuf, g_a);
    cudaGetSymbolAddress((void**)&uv,   g_uv);
    cudaGetSymbolAddress((void**)&vv,   g_vv);
    cudaGetSymbolAddress((void**)&vn,   g_vn);
    cudaGetSymbolAddress((void**)&cnt,  g_cnt);

    float* outV = (out_size >= NN*FD + NN*FD*3) ? (outH + NN*FD) : Valt;

    cudaMemsetAsync(cnt,  0, NN*sizeof(int));
    cudaMemsetAsync(Sbar, 0, (size_t)NN*FD*sizeof(float));
    cudaMemsetAsync(V,    0, (size_t)NN*FD*3*sizeof(float));
    cudaMemsetAsync(Vb0,  0, (size_t)NN*FD*3*sizeof(float));
    cudaMemcpyAsync(outH, Hin, (size_t)NN*FD*sizeof(float),
                    cudaMemcpyDeviceToDevice);

    count_kernel<<<(NE+255)/256, 256>>>(nbr);
    scan_kernel<<<1, 1024>>>();
    fill_kernel<<<(NE+255)/256, 256>>>(nbr);
    sort_kernel<<<(NN+127)/128, 128>>>();
    edge_geom_kernel<<<(NE+127)/128, 128>>>(xyz, nbr);

    float* Vbufs[2] = {V,   outV};
    float* Bbufs[2] = {Vb0, Vb1};

    const int MT128 = (NN + 127) / 128;  // 79
    const int MT64  = (NN + 63) / 64;    // 157

    for (int l = 0; l < 3; l++) {
        const float* W1  = msg_W1 + (size_t)l*256*256;
        const float* b1  = msg_b1 + (size_t)l*256;
        const float* W2  = msg_W2 + (size_t)l*256*640;
        const float* b2  = msg_b2 + (size_t)l*640;
        const float* dWl = dist_W + (size_t)l*20*640;
        const float* dbl = dist_b + (size_t)l*640;
        const float* Ul  = upd_U  + (size_t)l*128*128;
        const float* Wtl = upd_Vw + (size_t)l*128*128;
        const float* uW1 = upd_W1 + (size_t)l*256*128;
        const float* ub1 = upd_b1 + (size_t)l*128;
        const float* uW2 = upd_W2 + (size_t)l*128*384;
        const float* ub2 = upd_b2 + (size_t)l*384;

        float* Vin   = Vbufs[l & 1];
        float* Vout_ = Vbufs[(l+1) & 1];
        float* Bin   = Bbufs[l & 1];
        float* Bout  = Bbufs[(l+1) & 1];

        // tmp = silu([H|Sbar] @ W1 + b1)   [10000,256]
        gemm_tc<128,1><<<dim3(256/128, MT128), 256>>>(outH, 128, Sbar, 128, 128,
                                                      W1, b1, tmp, NN, 256, 256);
        // phi = tmp @ W2 + b2              [10000,640]
        gemm_tc<128,0><<<dim3(640/128, MT128), 256>>>(tmp, 256, tmp, 256, 256,
                                                      W2, b2, phi, NN, 640, 256);
        // message aggregation
        agg_kernel<<<(NN+7)/8, 128>>>(phi, dWl, dbl, nbr,
                                      Vin, Vout_, Bin, Bout, outH, Sbar);
        // u_v, v_v, v_norm
        upd_uv_kernel<<<NN/4, 128>>>(Vout_, Ul, Wtl, uv, vv, vn);
        // t2 = silu([H|v_norm] @ uW1 + ub1)  [10000,128] -> BM=64 for occupancy
        gemm_tc<64,1><<<dim3(128/128, MT64), 128>>>(outH, 128, vn, 128, 128,
                                                    uW1, ub1, t2, NN, 128, 256);
        // a = t2 @ uW2 + ub2               [10000,384]
        gemm_tc<128,0><<<dim3(384/128, MT128), 256>>>(t2, 128, t2, 128, 128,
                                                      uW2, ub2, aBuf, NN, 384, 128);
        // H += a1*dot + a2 ; V += a0*u_v
        final_upd_kernel<<<(NN*128+255)/256, 256>>>(outH, Vout_, uv, vv, aBuf);
    }
}